// round 7
// baseline (speedup 1.0000x reference)
#include <cuda_runtime.h>
#include <math.h>
#include <limits.h>

#define NN   100000
#define EE   1600000
#define FIN  128
#define EDIM 16
#define NH1  8
#define HID  16
#define D1   128    // NH1*HID
#define C2   16     // NUM_CLASSES

// ------------------------- scratch (device globals; no allocs) ---------------
__device__ __align__(16) float g_xh1[(size_t)NN * 128];
__device__ __align__(16) float g_as1[(size_t)NN * 8];
__device__ __align__(16) float g_ad1[(size_t)NN * 8];
__device__ __align__(16) int   g_m1 [(size_t)NN * 8];
__device__ __align__(16) float g_s1 [(size_t)NN * 8];
__device__ __align__(16) float g_alpha1[(size_t)EE * 8];
__device__ __align__(16) float g_ae2e[(size_t)EE];
__device__ __align__(16) float g_acc1[(size_t)NN * 128];
__device__ __align__(16) float g_h1 [(size_t)NN * 128];
__device__ __align__(16) float g_xh2[(size_t)NN * 16];
__device__ __align__(16) float g_as2[(size_t)NN];
__device__ __align__(16) float g_ad2[(size_t)NN];
__device__ __align__(16) int   g_m2 [(size_t)NN];
__device__ __align__(16) float g_s2 [(size_t)NN];
__device__ __align__(16) float g_alpha2[(size_t)EE];
__device__ __align__(16) float g_acc2[(size_t)NN * 16];
__device__ __align__(16) float g_Ae1[16 * 8];
__device__ __align__(16) float g_ae2w[16];
__device__ __align__(16) int2  g_sd[(size_t)EE];   // canonical (src, dst) int32
__device__ int g_is64;

// ------------------------- helpers -------------------------------------------
__device__ __forceinline__ int enc_f(float f) {
    int i = __float_as_int(f);
    return i >= 0 ? i : (i ^ 0x7FFFFFFF);
}
__device__ __forceinline__ float dec_f(int i) {
    return __int_as_float(i >= 0 ? i : (i ^ 0x7FFFFFFF));
}
__device__ __forceinline__ void red_add_v4(float* p, float4 v) {
    asm volatile("red.global.add.v4.f32 [%0], {%1,%2,%3,%4};"
                 :: "l"(p), "f"(v.x), "f"(v.y), "f"(v.z), "f"(v.w) : "memory");
}
__device__ __forceinline__ float lrelu(float a) { return a >= 0.f ? a : 0.2f * a; }

// ------------------------- edge_index dtype detection ------------------------
// int64 node ids are < 2^31 => every high int32 word is 0.
// int32 ids are random in [0, 100000): 64 consecutive odd words all zero is
// impossible. Deterministic given the input.
__global__ void k_detect(const int* __restrict__ eib) {
    if (threadIdx.x == 0) {
        int all0 = 1;
        #pragma unroll 8
        for (int i = 0; i < 64; ++i)
            if (eib[2 * i + 1] != 0) all0 = 0;
        g_is64 = all0;
    }
}

// Canonicalize edge index to int2 (src, dst), handling either dtype.
__global__ void k_gather(const void* __restrict__ eiv) {
    int e = blockIdx.x * 256 + threadIdx.x;
    if (e >= EE) return;
    int s, d;
    if (g_is64) {
        const long long* p = (const long long*)eiv;
        s = (int)p[e];
        d = (int)p[(size_t)EE + e];
    } else {
        const int* p = (const int*)eiv;
        s = p[e];
        d = p[(size_t)EE + e];
    }
    g_sd[e] = make_int2(s, d);
}

// ------------------------- init ----------------------------------------------
__global__ void k_init() {
    int i = blockIdx.x * 256 + threadIdx.x;
    if (i < NN * 128) g_acc1[i] = 0.f;
    if (i < NN * 16)  g_acc2[i] = 0.f;
    if (i < NN * 8) { g_s1[i] = 0.f; g_m1[i] = INT_MIN; }
    if (i < NN)     { g_s2[i] = 0.f; g_m2[i] = INT_MIN; }
}

// ------------------------- precompute folded edge weights --------------------
__global__ void k_pre(const float* __restrict__ We1, const float* __restrict__ atte1,
                      const float* __restrict__ We2, const float* __restrict__ atte2) {
    int t = threadIdx.x;
    if (t < 128) {
        int d = t >> 3, h = t & 7;
        float s = 0.f;
        #pragma unroll
        for (int c = 0; c < 16; ++c) s += We1[d * 128 + h * 16 + c] * atte1[h * 16 + c];
        g_Ae1[t] = s;  // [d][h], index d*8+h == t
    }
    if (t < 16) {
        float s = 0.f;
        #pragma unroll
        for (int c = 0; c < 16; ++c) s += We2[t * 16 + c] * atte2[c];
        g_ae2w[t] = s;
    }
}

// ------------------------- GEMM1: xh1 = X @ W1  (100k x 128 x 128) ----------
// grid (ceil(N/64), 2), 256 thr; K tiled by 64; static smem only (34.8KB)
__global__ __launch_bounds__(256) void k_gemm1(const float* __restrict__ X,
                                               const float* __restrict__ W) {
    __shared__ float xs[64 * 72];   // [64 rows][64 k + pad 8]
    __shared__ float ws[64 * 64];   // [64 k][64 cols]
    int rb = blockIdx.x * 64;
    int cb = blockIdx.y * 64;
    int t = threadIdx.x;
    int tc = t & 15, tr = t >> 4;

    float acc[4][4];
    #pragma unroll
    for (int i = 0; i < 4; ++i)
        #pragma unroll
        for (int j = 0; j < 4; ++j) acc[i][j] = 0.f;

    for (int kt = 0; kt < 128; kt += 64) {
        __syncthreads();
        // load X tile: 64 rows x 64 k-floats -> 1024 float4, 4 per thread
        for (int i = t; i < 64 * 16; i += 256) {
            int r = i >> 4, c4 = i & 15;
            int row = rb + r;
            float4 v = make_float4(0.f, 0.f, 0.f, 0.f);
            if (row < NN) v = *(const float4*)(X + (size_t)row * 128 + kt + c4 * 4);
            *(float4*)(xs + r * 72 + c4 * 4) = v;
        }
        // load W tile: 64 k x 64 cols
        for (int i = t; i < 64 * 16; i += 256) {
            int k = i >> 4, c4 = i & 15;
            *(float4*)(ws + k * 64 + c4 * 4) =
                *(const float4*)(W + (size_t)(kt + k) * 128 + cb + c4 * 4);
        }
        __syncthreads();
        #pragma unroll 4
        for (int k = 0; k < 64; ++k) {
            float4 w4 = *(const float4*)(ws + k * 64 + tc * 4);
            float a0 = xs[(tr * 4 + 0) * 72 + k];
            float a1 = xs[(tr * 4 + 1) * 72 + k];
            float a2 = xs[(tr * 4 + 2) * 72 + k];
            float a3 = xs[(tr * 4 + 3) * 72 + k];
            acc[0][0] += a0 * w4.x; acc[0][1] += a0 * w4.y; acc[0][2] += a0 * w4.z; acc[0][3] += a0 * w4.w;
            acc[1][0] += a1 * w4.x; acc[1][1] += a1 * w4.y; acc[1][2] += a1 * w4.z; acc[1][3] += a1 * w4.w;
            acc[2][0] += a2 * w4.x; acc[2][1] += a2 * w4.y; acc[2][2] += a2 * w4.z; acc[2][3] += a2 * w4.w;
            acc[3][0] += a3 * w4.x; acc[3][1] += a3 * w4.y; acc[3][2] += a3 * w4.z; acc[3][3] += a3 * w4.w;
        }
    }
    #pragma unroll
    for (int i = 0; i < 4; ++i) {
        int row = rb + tr * 4 + i;
        if (row < NN)
            *(float4*)(g_xh1 + (size_t)row * 128 + cb + tc * 4) =
                make_float4(acc[i][0], acc[i][1], acc[i][2], acc[i][3]);
    }
}

// ------------------------- per-(node,head) attention scores, layer 1 ---------
__global__ void k_att1(const float* __restrict__ atts, const float* __restrict__ attd) {
    int tid = blockIdx.x * 256 + threadIdx.x;
    if (tid >= NN * 8) return;
    int h = tid & 7, n = tid >> 3;
    const float4* p = (const float4*)(g_xh1 + (size_t)n * 128 + h * 16);
    const float4* a = (const float4*)(atts + h * 16);
    const float4* b = (const float4*)(attd + h * 16);
    float s = 0.f, d = 0.f;
    #pragma unroll
    for (int j = 0; j < 4; ++j) {
        float4 x = p[j], av = a[j], bv = b[j];
        s += x.x * av.x + x.y * av.y + x.z * av.z + x.w * av.w;
        d += x.x * bv.x + x.y * bv.y + x.z * bv.z + x.w * bv.w;
    }
    g_as1[tid] = s;
    g_ad1[tid] = d;
}

// ------------------------- edge pass A (layer-1 logits + segment max) --------
__global__ __launch_bounds__(256) void k_edgeA(const float* __restrict__ ea) {
    __shared__ float sA[128];
    __shared__ float sE[16];
    int t = threadIdx.x;
    if (t < 128) sA[t] = g_Ae1[t];
    if (t < 16)  sE[t] = g_ae2w[t];
    __syncthreads();
    int e = blockIdx.x * 256 + t;
    if (e >= EE) return;
    int2 sd = g_sd[e];
    int s = sd.x, d = sd.y;
    float ev[16];
    {
        const float4* ep = (const float4*)(ea + (size_t)e * 16);
        ((float4*)ev)[0] = ep[0]; ((float4*)ev)[1] = ep[1];
        ((float4*)ev)[2] = ep[2]; ((float4*)ev)[3] = ep[3];
    }
    float aeh[8] = {0, 0, 0, 0, 0, 0, 0, 0};
    float a2 = 0.f;
    #pragma unroll
    for (int dd = 0; dd < 16; ++dd) {
        float v = ev[dd];
        a2 += v * sE[dd];
        #pragma unroll
        for (int h = 0; h < 8; ++h) aeh[h] += v * sA[dd * 8 + h];
    }
    float4 s0 = *(const float4*)(g_as1 + (size_t)s * 8);
    float4 s1v = *(const float4*)(g_as1 + (size_t)s * 8 + 4);
    float4 d0 = *(const float4*)(g_ad1 + (size_t)d * 8);
    float4 d1v = *(const float4*)(g_ad1 + (size_t)d * 8 + 4);
    float al[8];
    al[0] = lrelu(s0.x + d0.x + aeh[0]);  al[1] = lrelu(s0.y + d0.y + aeh[1]);
    al[2] = lrelu(s0.z + d0.z + aeh[2]);  al[3] = lrelu(s0.w + d0.w + aeh[3]);
    al[4] = lrelu(s1v.x + d1v.x + aeh[4]); al[5] = lrelu(s1v.y + d1v.y + aeh[5]);
    al[6] = lrelu(s1v.z + d1v.z + aeh[6]); al[7] = lrelu(s1v.w + d1v.w + aeh[7]);
    *(float4*)(g_alpha1 + (size_t)e * 8)     = make_float4(al[0], al[1], al[2], al[3]);
    *(float4*)(g_alpha1 + (size_t)e * 8 + 4) = make_float4(al[4], al[5], al[6], al[7]);
    g_ae2e[e] = a2;
    #pragma unroll
    for (int h = 0; h < 8; ++h) atomicMax(g_m1 + (size_t)d * 8 + h, enc_f(al[h]));
}

// ------------------------- edge pass B (exp + denom + message scatter) -------
// warp per edge; lane*4 covers the 128-float message
__global__ __launch_bounds__(256) void k_edgeB() {
    int gw = (blockIdx.x * 256 + threadIdx.x) >> 5;
    int lane = threadIdx.x & 31;
    if (gw >= EE) return;
    size_t e = (size_t)gw;
    int2 sd = g_sd[e];
    int s = sd.x, d = sd.y;
    int h = lane & 7;
    float a = g_alpha1[e * 8 + h];
    float m = dec_f(g_m1[(size_t)d * 8 + h]);
    float ex = __expf(a - m);
    if (lane < 8) atomicAdd(g_s1 + (size_t)d * 8 + lane, ex);
    float w = __shfl_sync(0xffffffffu, ex, lane >> 2);
    float4 v = *(const float4*)(g_xh1 + (size_t)s * 128 + lane * 4);
    v.x *= w; v.y *= w; v.z *= w; v.w *= w;
    red_add_v4(g_acc1 + (size_t)d * 128 + lane * 4, v);
}

// ------------------------- normalize + bias + ELU -> h1 ----------------------
__global__ void k_h1(const float* __restrict__ b1) {
    int tid = blockIdx.x * 256 + threadIdx.x;
    if (tid >= NN * 32) return;
    int n = tid >> 5, q = tid & 31;
    float4 a = *(const float4*)(g_acc1 + (size_t)n * 128 + q * 4);
    float s = g_s1[(size_t)n * 8 + (q >> 2)] + 1e-16f;
    float4 b = *(const float4*)(b1 + q * 4);
    float4 o;
    o.x = a.x / s + b.x; o.y = a.y / s + b.y; o.z = a.z / s + b.z; o.w = a.w / s + b.w;
    o.x = o.x > 0.f ? o.x : expm1f(o.x);
    o.y = o.y > 0.f ? o.y : expm1f(o.y);
    o.z = o.z > 0.f ? o.z : expm1f(o.z);
    o.w = o.w > 0.f ? o.w : expm1f(o.w);
    *(float4*)(g_h1 + (size_t)n * 128 + q * 4) = o;
}

// ------------------------- GEMM2: xh2 = h1 @ W2, plus a_s2/a_d2 --------------
__global__ __launch_bounds__(256) void k_gemm2(const float* __restrict__ W2,
                                               const float* __restrict__ atts,
                                               const float* __restrict__ attd) {
    __shared__ float xs[64 * 132];
    __shared__ float ws[128 * 16];
    __shared__ float sh2[64 * 16];
    __shared__ float sa[16], sdv[16];
    int rb = blockIdx.x * 64;
    int t = threadIdx.x;
    {
        int lane = t & 31, w0 = t >> 5;
        for (int r = w0; r < 64; r += 8) {
            int row = rb + r;
            float4 v = make_float4(0.f, 0.f, 0.f, 0.f);
            if (row < NN) v = ((const float4*)(g_h1 + (size_t)row * 128))[lane];
            *(float4*)(xs + r * 132 + lane * 4) = v;
        }
    }
    for (int i = t; i < 128 * 4; i += 256) {
        int k = i >> 2, c4 = i & 3;
        *(float4*)(ws + k * 16 + c4 * 4) = *(const float4*)(W2 + k * 16 + c4 * 4);
    }
    if (t < 16) { sa[t] = atts[t]; sdv[t] = attd[t]; }
    __syncthreads();
    int tc = t & 15, tr = t >> 4;
    float acc[4] = {0, 0, 0, 0};
    #pragma unroll 4
    for (int k = 0; k < 128; ++k) {
        float w = ws[k * 16 + tc];
        acc[0] += xs[(tr * 4 + 0) * 132 + k] * w;
        acc[1] += xs[(tr * 4 + 1) * 132 + k] * w;
        acc[2] += xs[(tr * 4 + 2) * 132 + k] * w;
        acc[3] += xs[(tr * 4 + 3) * 132 + k] * w;
    }
    #pragma unroll
    for (int i = 0; i < 4; ++i) {
        int r = tr * 4 + i, row = rb + r;
        sh2[r * 16 + tc] = acc[i];
        if (row < NN) g_xh2[(size_t)row * 16 + tc] = acc[i];
    }
    __syncthreads();
    if (t < 64) {
        int row = rb + t;
        if (row < NN) {
            float s = 0.f, d = 0.f;
            #pragma unroll
            for (int c = 0; c < 16; ++c) {
                float v = sh2[t * 16 + c];
                s += v * sa[c];
                d += v * sdv[c];
            }
            g_as2[row] = s;
            g_ad2[row] = d;
        }
    }
}

// ------------------------- edge pass C (layer-2 logits + max) ----------------
__global__ void k_edgeC() {
    int e = blockIdx.x * 256 + threadIdx.x;
    if (e >= EE) return;
    int2 sd = g_sd[e];
    float a = lrelu(g_as2[sd.x] + g_ad2[sd.y] + g_ae2e[e]);
    g_alpha2[e] = a;
    atomicMax(g_m2 + sd.y, enc_f(a));
}

// ------------------------- edge pass D (exp + denom + message scatter) -------
__global__ void k_edgeD() {
    int e = blockIdx.x * 256 + threadIdx.x;
    if (e >= EE) return;
    int2 sd = g_sd[e];
    int s = sd.x, d = sd.y;
    float ex = __expf(g_alpha2[e] - dec_f(g_m2[d]));
    atomicAdd(g_s2 + d, ex);
    const float4* xp = (const float4*)(g_xh2 + (size_t)s * 16);
    #pragma unroll
    for (int j = 0; j < 4; ++j) {
        float4 v = xp[j];
        v.x *= ex; v.y *= ex; v.z *= ex; v.w *= ex;
        red_add_v4(g_acc2 + (size_t)d * 16 + j * 4, v);
    }
}

// ------------------------- final: normalize + bias + log_softmax -------------
__global__ void k_final(const float* __restrict__ b2, float* __restrict__ out) {
    int n = blockIdx.x * 256 + threadIdx.x;
    if (n >= NN) return;
    float s = g_s2[n] + 1e-16f;
    float o[16];
    #pragma unroll
    for (int j = 0; j < 4; ++j) {
        float4 v = ((const float4*)(g_acc2 + (size_t)n * 16))[j];
        float4 b = ((const float4*)b2)[j];
        o[j * 4 + 0] = v.x / s + b.x;
        o[j * 4 + 1] = v.y / s + b.y;
        o[j * 4 + 2] = v.z / s + b.z;
        o[j * 4 + 3] = v.w / s + b.w;
    }
    float m = o[0];
    #pragma unroll
    for (int c = 1; c < 16; ++c) m = fmaxf(m, o[c]);
    float sum = 0.f;
    #pragma unroll
    for (int c = 0; c < 16; ++c) sum += __expf(o[c] - m);
    float l = m + logf(sum);
    #pragma unroll
    for (int j = 0; j < 4; ++j) {
        float4 v = make_float4(o[j * 4 + 0] - l, o[j * 4 + 1] - l,
                               o[j * 4 + 2] - l, o[j * 4 + 3] - l);
        ((float4*)(out + (size_t)n * 16))[j] = v;
    }
}

// ------------------------- launch --------------------------------------------
extern "C" void kernel_launch(void* const* d_in, const int* in_sizes, int n_in,
                              void* d_out, int out_size) {
    const float* x     = (const float*)d_in[0];
    const void*  ei    = d_in[1];                    // int32 or int64, detected on device
    const float* ea    = (const float*)d_in[2];
    const float* W1    = (const float*)d_in[3];
    const float* atts1 = (const float*)d_in[4];
    const float* attd1 = (const float*)d_in[5];
    const float* We1   = (const float*)d_in[6];
    const float* atte1 = (const float*)d_in[7];
    const float* b1    = (const float*)d_in[8];
    const float* W2    = (const float*)d_in[9];
    const float* atts2 = (const float*)d_in[10];
    const float* attd2 = (const float*)d_in[11];
    const float* We2   = (const float*)d_in[12];
    const float* atte2 = (const float*)d_in[13];
    const float* b2    = (const float*)d_in[14];
    float* out = (float*)d_out;

    k_detect<<<1, 32>>>((const int*)ei);
    k_gather<<<(EE + 255) / 256, 256>>>(ei);
    k_init<<<(NN * 128 + 255) / 256, 256>>>();
    k_pre<<<1, 128>>>(We1, atte1, We2, atte2);

    k_gemm1<<<dim3((NN + 63) / 64, 2), 256>>>(x, W1);

    k_att1<<<(NN * 8 + 255) / 256, 256>>>(atts1, attd1);
    k_edgeA<<<(EE + 255) / 256, 256>>>(ea);
    k_edgeB<<<(EE * 32) / 256, 256>>>();
    k_h1<<<(NN * 32 + 255) / 256, 256>>>(b1);
    k_gemm2<<<(NN + 63) / 64, 256>>>(W2, atts2, attd2);
    k_edgeC<<<(EE + 255) / 256, 256>>>();
    k_edgeD<<<(EE + 255) / 256, 256>>>();
    k_final<<<(NN + 255) / 256, 256>>>(b2, out);
}

// round 11
// speedup vs baseline: 2.1110x; 2.1110x over previous
#include <cuda_runtime.h>
#include <math.h>
#include <limits.h>

#define NN   100000
#define EE   1600000
#define FIN  128
#define EDIM 16
#define NH1  8
#define HID  16
#define D1   128
#define C2   16
#define NB1  98          // ceil(NN / 1024)

// ------------------------- scratch (device globals; no allocs) ---------------
__device__ __align__(16) float g_xh1[(size_t)NN * 128];
__device__ __align__(16) float g_as1[(size_t)NN * 8];
__device__ __align__(16) float g_ad1[(size_t)NN * 8];
__device__ __align__(16) float g_alpha1[(size_t)EE * 8];
__device__ __align__(16) float g_ae2e[(size_t)EE];
__device__ __align__(16) float g_h1 [(size_t)NN * 128];
__device__ __align__(16) float g_xh2[(size_t)NN * 16];
__device__ __align__(16) float g_as2[(size_t)NN];
__device__ __align__(16) float g_ad2[(size_t)NN];
__device__ __align__(16) float g_alpha2[(size_t)EE];
__device__ __align__(16) float g_Ae1[16 * 8];
__device__ __align__(16) float g_ae2w[16];
__device__ __align__(16) int2  g_sd [(size_t)EE];     // canonical (src, dst)
__device__ __align__(16) int2  g_csr[(size_t)EE];     // (src, edge-id) grouped by dst
__device__ __align__(16) int   g_deg[NN];
__device__ __align__(16) int   g_partial[NN];
__device__ __align__(16) int   g_bsum[NB1];
__device__ __align__(16) int   g_boff[NB1];
__device__ __align__(16) int   g_rowptr[NN + 1];
__device__ __align__(16) int   g_cur[NN];
__device__ int g_gm1i;     // global max of layer-1 logits (enc_f encoded)
__device__ int g_gm2i;     // global max of layer-2 logits
__device__ int g_is64;

// ------------------------- helpers -------------------------------------------
__device__ __forceinline__ int enc_f(float f) {
    int i = __float_as_int(f);
    return i >= 0 ? i : (i ^ 0x7FFFFFFF);
}
__device__ __forceinline__ float dec_f(int i) {
    return __int_as_float(i >= 0 ? i : (i ^ 0x7FFFFFFF));
}
__device__ __forceinline__ float lrelu(float a) { return a >= 0.f ? a : 0.2f * a; }

// ------------------------- edge_index dtype detection ------------------------
__global__ void k_detect(const int* __restrict__ eib) {
    if (threadIdx.x == 0) {
        int all0 = 1;
        #pragma unroll 8
        for (int i = 0; i < 64; ++i)
            if (eib[2 * i + 1] != 0) all0 = 0;
        g_is64 = all0;
    }
}

// ------------------------- zero counters --------------------------------------
__global__ void k_zero() {
    int i = blockIdx.x * 256 + threadIdx.x;
    if (i < NN) g_deg[i] = 0;
    if (i == 0) { g_gm1i = INT_MIN; g_gm2i = INT_MIN; }
}

// ------------------------- canonicalize + histogram ---------------------------
__global__ void k_gather(const void* __restrict__ eiv) {
    int e = blockIdx.x * 256 + threadIdx.x;
    if (e >= EE) return;
    int s, d;
    if (g_is64) {
        const long long* p = (const long long*)eiv;
        s = (int)p[e];
        d = (int)p[(size_t)EE + e];
    } else {
        const int* p = (const int*)eiv;
        s = p[e];
        d = p[(size_t)EE + e];
    }
    g_sd[e] = make_int2(s, d);
    atomicAdd(g_deg + d, 1);
}

// ------------------------- 2-level exclusive scan of degrees -------------------
__global__ __launch_bounds__(1024) void k_scan1() {
    __shared__ int sm[1024];
    int t = threadIdx.x, b = blockIdx.x;
    int i = b * 1024 + t;
    int v = (i < NN) ? g_deg[i] : 0;
    sm[t] = v;
    __syncthreads();
    for (int off = 1; off < 1024; off <<= 1) {
        int x = (t >= off) ? sm[t - off] : 0;
        __syncthreads();
        sm[t] += x;
        __syncthreads();
    }
    if (i < NN) g_partial[i] = sm[t];
    if (t == 1023) g_bsum[b] = sm[t];
}
__global__ void k_scan2() {
    __shared__ int sm[128];
    int t = threadIdx.x;
    sm[t] = (t < NB1) ? g_bsum[t] : 0;
    __syncthreads();
    for (int off = 1; off < 128; off <<= 1) {
        int x = (t >= off) ? sm[t - off] : 0;
        __syncthreads();
        sm[t] += x;
        __syncthreads();
    }
    if (t < NB1) g_boff[t] = sm[t];
}
__global__ __launch_bounds__(1024) void k_scan3() {
    int t = threadIdx.x, b = blockIdx.x;
    int i = b * 1024 + t;
    if (i >= NN) return;
    int base = (b > 0) ? g_boff[b - 1] : 0;
    int incl = g_partial[i] + base;
    g_rowptr[i + 1] = incl;
    g_cur[i] = incl - g_deg[i];
    if (i == 0) g_rowptr[0] = 0;
}
__global__ void k_scatter() {
    int e = blockIdx.x * 256 + threadIdx.x;
    if (e >= EE) return;
    int2 sd = g_sd[e];
    int pos = atomicAdd(g_cur + sd.y, 1);
    g_csr[pos] = make_int2(sd.x, e);
}

// ------------------------- precompute folded edge weights --------------------
__global__ void k_pre(const float* __restrict__ We1, const float* __restrict__ atte1,
                      const float* __restrict__ We2, const float* __restrict__ atte2) {
    int t = threadIdx.x;
    if (t < 128) {
        int d = t >> 3, h = t & 7;
        float s = 0.f;
        #pragma unroll
        for (int c = 0; c < 16; ++c) s += We1[d * 128 + h * 16 + c] * atte1[h * 16 + c];
        g_Ae1[t] = s;
    }
    if (t < 16) {
        float s = 0.f;
        #pragma unroll
        for (int c = 0; c < 16; ++c) s += We2[t * 16 + c] * atte2[c];
        g_ae2w[t] = s;
    }
}

// ------------------------- GEMM1: xh1 = X @ W1 (full 128 cols per block) -----
__global__ __launch_bounds__(256) void k_gemm1(const float* __restrict__ X,
                                               const float* __restrict__ W) {
    __shared__ float xs[64 * 36];    // 64 rows x (32 k + 4 pad)
    __shared__ float ws[32 * 128];   // 32 k x 128 cols
    int rb = blockIdx.x * 64;
    int t = threadIdx.x;
    int tc = t & 15, tr = t >> 4;

    float acc[4][8];
    #pragma unroll
    for (int i = 0; i < 4; ++i)
        #pragma unroll
        for (int j = 0; j < 8; ++j) acc[i][j] = 0.f;

    for (int kt = 0; kt < 128; kt += 32) {
        __syncthreads();
        #pragma unroll
        for (int i = t; i < 512; i += 256) {       // X tile: 64x32 = 512 float4
            int r = i >> 3, c4 = i & 7;
            int row = rb + r;
            float4 v = make_float4(0.f, 0.f, 0.f, 0.f);
            if (row < NN) v = *(const float4*)(X + (size_t)row * 128 + kt + c4 * 4);
            *(float4*)(xs + r * 36 + c4 * 4) = v;
        }
        #pragma unroll
        for (int i = t; i < 1024; i += 256) {      // W tile: 32x128 = 1024 float4
            int k = i >> 5, c4 = i & 31;
            *(float4*)(ws + k * 128 + c4 * 4) =
                *(const float4*)(W + (size_t)(kt + k) * 128 + c4 * 4);
        }
        __syncthreads();
        #pragma unroll 8
        for (int k = 0; k < 32; ++k) {
            float4 w0 = *(const float4*)(ws + k * 128 + tc * 8);
            float4 w1 = *(const float4*)(ws + k * 128 + tc * 8 + 4);
            #pragma unroll
            for (int i = 0; i < 4; ++i) {
                float a = xs[(tr * 4 + i) * 36 + k];
                acc[i][0] += a * w0.x; acc[i][1] += a * w0.y;
                acc[i][2] += a * w0.z; acc[i][3] += a * w0.w;
                acc[i][4] += a * w1.x; acc[i][5] += a * w1.y;
                acc[i][6] += a * w1.z; acc[i][7] += a * w1.w;
            }
        }
    }
    #pragma unroll
    for (int i = 0; i < 4; ++i) {
        int row = rb + tr * 4 + i;
        if (row < NN) {
            *(float4*)(g_xh1 + (size_t)row * 128 + tc * 8) =
                make_float4(acc[i][0], acc[i][1], acc[i][2], acc[i][3]);
            *(float4*)(g_xh1 + (size_t)row * 128 + tc * 8 + 4) =
                make_float4(acc[i][4], acc[i][5], acc[i][6], acc[i][7]);
        }
    }
}

// ------------------------- per-(node,head) attention scores, layer 1 ---------
__global__ void k_att1(const float* __restrict__ atts, const float* __restrict__ attd) {
    int tid = blockIdx.x * 256 + threadIdx.x;
    if (tid >= NN * 8) return;
    int h = tid & 7, n = tid >> 3;
    const float4* p = (const float4*)(g_xh1 + (size_t)n * 128 + h * 16);
    const float4* a = (const float4*)(atts + h * 16);
    const float4* b = (const float4*)(attd + h * 16);
    float s = 0.f, d = 0.f;
    #pragma unroll
    for (int j = 0; j < 4; ++j) {
        float4 x = p[j], av = a[j], bv = b[j];
        s += x.x * av.x + x.y * av.y + x.z * av.z + x.w * av.w;
        d += x.x * bv.x + x.y * bv.y + x.z * bv.z + x.w * bv.w;
    }
    g_as1[tid] = s;
    g_ad1[tid] = d;
}

// ------------------------- edge pass A: layer-1 logits + global max ----------
__global__ __launch_bounds__(256) void k_edgeA(const float* __restrict__ ea) {
    __shared__ float sA[128];
    __shared__ float sE[16];
    __shared__ float wmax[8];
    int t = threadIdx.x;
    if (t < 128) sA[t] = g_Ae1[t];
    if (t < 16)  sE[t] = g_ae2w[t];
    __syncthreads();
    int e = blockIdx.x * 256 + t;
    float mt = -1e30f;
    if (e < EE) {
        int2 sd = g_sd[e];
        int s = sd.x, d = sd.y;
        float ev[16];
        {
            const float4* ep = (const float4*)(ea + (size_t)e * 16);
            ((float4*)ev)[0] = ep[0]; ((float4*)ev)[1] = ep[1];
            ((float4*)ev)[2] = ep[2]; ((float4*)ev)[3] = ep[3];
        }
        float aeh[8] = {0, 0, 0, 0, 0, 0, 0, 0};
        float a2 = 0.f;
        #pragma unroll
        for (int dd = 0; dd < 16; ++dd) {
            float v = ev[dd];
            a2 += v * sE[dd];
            #pragma unroll
            for (int h = 0; h < 8; ++h) aeh[h] += v * sA[dd * 8 + h];
        }
        float4 s0 = *(const float4*)(g_as1 + (size_t)s * 8);
        float4 s1v = *(const float4*)(g_as1 + (size_t)s * 8 + 4);
        float4 d0 = *(const float4*)(g_ad1 + (size_t)d * 8);
        float4 d1v = *(const float4*)(g_ad1 + (size_t)d * 8 + 4);
        float al[8];
        al[0] = lrelu(s0.x + d0.x + aeh[0]);   al[1] = lrelu(s0.y + d0.y + aeh[1]);
        al[2] = lrelu(s0.z + d0.z + aeh[2]);   al[3] = lrelu(s0.w + d0.w + aeh[3]);
        al[4] = lrelu(s1v.x + d1v.x + aeh[4]); al[5] = lrelu(s1v.y + d1v.y + aeh[5]);
        al[6] = lrelu(s1v.z + d1v.z + aeh[6]); al[7] = lrelu(s1v.w + d1v.w + aeh[7]);
        *(float4*)(g_alpha1 + (size_t)e * 8)     = make_float4(al[0], al[1], al[2], al[3]);
        *(float4*)(g_alpha1 + (size_t)e * 8 + 4) = make_float4(al[4], al[5], al[6], al[7]);
        g_ae2e[e] = a2;
        #pragma unroll
        for (int h = 0; h < 8; ++h) mt = fmaxf(mt, al[h]);
    }
    // block max -> one atomic (softmax is shift-invariant; global shift is exact)
    #pragma unroll
    for (int off = 16; off > 0; off >>= 1)
        mt = fmaxf(mt, __shfl_xor_sync(0xffffffffu, mt, off));
    if ((t & 31) == 0) wmax[t >> 5] = mt;
    __syncthreads();
    if (t < 8) {
        float v = wmax[t];
        #pragma unroll
        for (int off = 4; off > 0; off >>= 1)
            v = fmaxf(v, __shfl_xor_sync(0x000000ffu, v, off));
        if (t == 0) atomicMax(&g_gm1i, enc_f(v));
    }
}

// ------------------------- layer-1 aggregation: warp per dst -----------------
// single pass: ex = exp(alpha - gmax); acc128 in regs; fused norm+bias+ELU
__global__ __launch_bounds__(256) void k_agg1(const float* __restrict__ b1) {
    int gw = (blockIdx.x * 256 + threadIdx.x) >> 5;
    int lane = threadIdx.x & 31;
    if (gw >= NN) return;
    int d = gw;
    int start = g_rowptr[d], end = g_rowptr[d + 1];
    float gm = dec_f(g_gm1i);
    float sum = 0.f;
    float4 acc = make_float4(0.f, 0.f, 0.f, 0.f);
    for (int j = start; j < end; ++j) {
        int2 se = g_csr[j];
        float aval = (lane < 8) ? g_alpha1[(size_t)se.y * 8 + lane] : 0.f;
        float ex = __expf(aval - gm);
        if (lane < 8) sum += ex;
        float w = __shfl_sync(0xffffffffu, ex, lane >> 2);
        float4 v = *(const float4*)(g_xh1 + (size_t)se.x * 128 + lane * 4);
        acc.x += w * v.x; acc.y += w * v.y; acc.z += w * v.z; acc.w += w * v.w;
    }
    float s = __shfl_sync(0xffffffffu, sum, lane >> 2) + 1e-16f;
    float4 b = *(const float4*)(b1 + lane * 4);
    float4 o;
    o.x = acc.x / s + b.x; o.y = acc.y / s + b.y;
    o.z = acc.z / s + b.z; o.w = acc.w / s + b.w;
    o.x = o.x > 0.f ? o.x : expm1f(o.x);
    o.y = o.y > 0.f ? o.y : expm1f(o.y);
    o.z = o.z > 0.f ? o.z : expm1f(o.z);
    o.w = o.w > 0.f ? o.w : expm1f(o.w);
    *(float4*)(g_h1 + (size_t)d * 128 + lane * 4) = o;
}

// ------------------------- GEMM2: xh2 = h1 @ W2, plus a_s2/a_d2 --------------
__global__ __launch_bounds__(256) void k_gemm2(const float* __restrict__ W2,
                                               const float* __restrict__ atts,
                                               const float* __restrict__ attd) {
    __shared__ float xs[64 * 132];
    __shared__ float ws[128 * 16];
    __shared__ float sh2[64 * 16];
    __shared__ float sa[16], sdv[16];
    int rb = blockIdx.x * 64;
    int t = threadIdx.x;
    {
        int lane = t & 31, w0 = t >> 5;
        for (int r = w0; r < 64; r += 8) {
            int row = rb + r;
            float4 v = make_float4(0.f, 0.f, 0.f, 0.f);
            if (row < NN) v = ((const float4*)(g_h1 + (size_t)row * 128))[lane];
            *(float4*)(xs + r * 132 + lane * 4) = v;
        }
    }
    for (int i = t; i < 128 * 4; i += 256) {
        int k = i >> 2, c4 = i & 3;
        *(float4*)(ws + k * 16 + c4 * 4) = *(const float4*)(W2 + k * 16 + c4 * 4);
    }
    if (t < 16) { sa[t] = atts[t]; sdv[t] = attd[t]; }
    __syncthreads();
    int tc = t & 15, tr = t >> 4;
    float acc[4] = {0, 0, 0, 0};
    #pragma unroll 4
    for (int k = 0; k < 128; ++k) {
        float w = ws[k * 16 + tc];
        acc[0] += xs[(tr * 4 + 0) * 132 + k] * w;
        acc[1] += xs[(tr * 4 + 1) * 132 + k] * w;
        acc[2] += xs[(tr * 4 + 2) * 132 + k] * w;
        acc[3] += xs[(tr * 4 + 3) * 132 + k] * w;
    }
    #pragma unroll
    for (int i = 0; i < 4; ++i) {
        int r = tr * 4 + i, row = rb + r;
        sh2[r * 16 + tc] = acc[i];
        if (row < NN) g_xh2[(size_t)row * 16 + tc] = acc[i];
    }
    __syncthreads();
    if (t < 64) {
        int row = rb + t;
        if (row < NN) {
            float s = 0.f, d = 0.f;
            #pragma unroll
            for (int c = 0; c < 16; ++c) {
                float v = sh2[t * 16 + c];
                s += v * sa[c];
                d += v * sdv[c];
            }
            g_as2[row] = s;
            g_ad2[row] = d;
        }
    }
}

// ------------------------- edge pass C: layer-2 logits + global max ----------
__global__ __launch_bounds__(256) void k_edgeC() {
    __shared__ float wmax[8];
    int t = threadIdx.x;
    int e = blockIdx.x * 256 + t;
    float a = -1e30f;
    if (e < EE) {
        int2 sd = g_sd[e];
        a = lrelu(g_as2[sd.x] + g_ad2[sd.y] + g_ae2e[e]);
        g_alpha2[e] = a;
    }
    #pragma unroll
    for (int off = 16; off > 0; off >>= 1)
        a = fmaxf(a, __shfl_xor_sync(0xffffffffu, a, off));
    if ((t & 31) == 0) wmax[t >> 5] = a;
    __syncthreads();
    if (t < 8) {
        float v = wmax[t];
        #pragma unroll
        for (int off = 4; off > 0; off >>= 1)
            v = fmaxf(v, __shfl_xor_sync(0x000000ffu, v, off));
        if (t == 0) atomicMax(&g_gm2i, enc_f(v));
    }
}

// ------------------------- layer-2 aggregation + log_softmax -----------------
// 16-thread group per dst node
__global__ __launch_bounds__(256) void k_agg2(const float* __restrict__ b2,
                                              float* __restrict__ out) {
    int d = blockIdx.x * 16 + (threadIdx.x >> 4);
    int l = threadIdx.x & 15;
    if (d >= NN) return;
    int start = g_rowptr[d], end = g_rowptr[d + 1];
    float gm = dec_f(g_gm2i);
    float sum = 0.f, acc = 0.f;
    for (int j = start; j < end; ++j) {
        int2 se = g_csr[j];
        float ex = __expf(g_alpha2[se.y] - gm);
        sum += ex;
        acc += ex * g_xh2[(size_t)se.x * 16 + l];
    }
    float o = acc / (sum + 1e-16f) + b2[l];
    // log_softmax over the 16 classes within the group
    float m = o;
    #pragma unroll
    for (int off = 8; off > 0; off >>= 1)
        m = fmaxf(m, __shfl_xor_sync(0xffffffffu, m, off, 16));
    float e2 = __expf(o - m), s2 = e2;
    #pragma unroll
    for (int off = 8; off > 0; off >>= 1)
        s2 += __shfl_xor_sync(0xffffffffu, s2, off, 16);
    out[(size_t)d * 16 + l] = o - (m + logf(s2));
}

// ------------------------- launch --------------------------------------------
extern "C" void kernel_launch(void* const* d_in, const int* in_sizes, int n_in,
                              void* d_out, int out_size) {
    const float* x     = (const float*)d_in[0];
    const void*  ei    = d_in[1];
    const float* ea    = (const float*)d_in[2];
    const float* W1    = (const float*)d_in[3];
    const float* atts1 = (const float*)d_in[4];
    const float* attd1 = (const float*)d_in[5];
    const float* We1   = (const float*)d_in[6];
    const float* atte1 = (const float*)d_in[7];
    const float* b1    = (const float*)d_in[8];
    const float* W2    = (const float*)d_in[9];
    const float* atts2 = (const float*)d_in[10];
    const float* attd2 = (const float*)d_in[11];
    const float* We2   = (const float*)d_in[12];
    const float* atte2 = (const float*)d_in[13];
    const float* b2    = (const float*)d_in[14];
    float* out = (float*)d_out;

    k_detect<<<1, 32>>>((const int*)ei);
    k_zero<<<(NN + 255) / 256, 256>>>();
    k_gather<<<(EE + 255) / 256, 256>>>(ei);
    k_scan1<<<NB1, 1024>>>();
    k_scan2<<<1, 128>>>();
    k_scan3<<<NB1, 1024>>>();
    k_scatter<<<(EE + 255) / 256, 256>>>();
    k_pre<<<1, 128>>>(We1, atte1, We2, atte2);

    k_gemm1<<<(NN + 63) / 64, 256>>>(x, W1);
    k_att1<<<(NN * 8 + 255) / 256, 256>>>(atts1, attd1);
    k_edgeA<<<(EE + 255) / 256, 256>>>(ea);
    k_agg1<<<(NN * 32 + 255) / 256, 256>>>(b1);
    k_gemm2<<<(NN + 63) / 64, 256>>>(W2, atts2, attd2);
    k_edgeC<<<(EE + 255) / 256, 256>>>();
    k_agg2<<<(NN * 16 + 255) / 256, 256>>>(b2, out);
}

// round 12
// speedup vs baseline: 2.3138x; 1.0961x over previous
#include <cuda_runtime.h>
#include <math.h>
#include <limits.h>

#define NN   100000
#define EE   1600000
#define FIN  128
#define EDIM 16
#define NH1  8
#define HID  16
#define D1   128
#define C2   16
#define NB1  98          // ceil(NN / 1024)

typedef unsigned long long ull;

// ------------------------- scratch (device globals; no allocs) ---------------
__device__ __align__(16) float g_xh1[(size_t)NN * 128];
__device__ __align__(16) float g_as1[(size_t)NN * 8];
__device__ __align__(16) float g_ad1[(size_t)NN * 8];
__device__ __align__(16) float g_alpha1[(size_t)EE * 8];   // CSR order
__device__ __align__(16) float g_ae2e[(size_t)EE];         // CSR order
__device__ __align__(16) float g_h1 [(size_t)NN * 128];
__device__ __align__(16) float g_xh2[(size_t)NN * 16];
__device__ __align__(16) float g_as2[(size_t)NN];
__device__ __align__(16) float g_ad2[(size_t)NN];
__device__ __align__(16) float g_alpha2[(size_t)EE];       // CSR order
__device__ __align__(16) float g_Ae1[16 * 8];
__device__ __align__(16) float g_ae2w[16];
__device__ __align__(16) int2  g_sd [(size_t)EE];          // (src, dst) edge order
__device__ __align__(16) int2  g_csr[(size_t)EE];          // (src, dst) CSR order
__device__ __align__(16) int   g_eid[(size_t)EE];          // original edge id, CSR order
__device__ __align__(16) int   g_deg[NN];
__device__ __align__(16) int   g_partial[NN];
__device__ __align__(16) int   g_bsum[NB1];
__device__ __align__(16) int   g_boff[NB1];
__device__ __align__(16) int   g_rowptr[NN + 1];
__device__ __align__(16) int   g_cur[NN];
__device__ int g_gm1i;
__device__ int g_gm2i;
__device__ int g_is64;

// ------------------------- helpers -------------------------------------------
__device__ __forceinline__ int enc_f(float f) {
    int i = __float_as_int(f);
    return i >= 0 ? i : (i ^ 0x7FFFFFFF);
}
__device__ __forceinline__ float dec_f(int i) {
    return __int_as_float(i >= 0 ? i : (i ^ 0x7FFFFFFF));
}
__device__ __forceinline__ float lrelu(float a) { return a >= 0.f ? a : 0.2f * a; }

// packed f32x2 ops (sm_103a FFMA2 path)
__device__ __forceinline__ ull pk2(float lo, float hi) {
    ull d; asm("mov.b64 %0, {%1, %2};" : "=l"(d) : "f"(lo), "f"(hi)); return d;
}
__device__ __forceinline__ void fma2(ull& d, ull a, ull b) {
    asm("fma.rn.f32x2 %0, %1, %2, %0;" : "+l"(d) : "l"(a), "l"(b));
}
__device__ __forceinline__ float2 up2(ull d) {
    float2 r; asm("mov.b64 {%0, %1}, %2;" : "=f"(r.x), "=f"(r.y) : "l"(d)); return r;
}

// ------------------------- edge_index dtype detection ------------------------
__global__ void k_detect(const int* __restrict__ eib) {
    if (threadIdx.x == 0) {
        int all0 = 1;
        #pragma unroll 8
        for (int i = 0; i < 64; ++i)
            if (eib[2 * i + 1] != 0) all0 = 0;
        g_is64 = all0;
    }
}

__global__ void k_zero() {
    int i = blockIdx.x * 256 + threadIdx.x;
    if (i < NN) g_deg[i] = 0;
    if (i == 0) { g_gm1i = INT_MIN; g_gm2i = INT_MIN; }
}

// ------------------------- canonicalize + histogram ---------------------------
__global__ void k_gather(const void* __restrict__ eiv) {
    int e = blockIdx.x * 256 + threadIdx.x;
    if (e >= EE) return;
    int s, d;
    if (g_is64) {
        const long long* p = (const long long*)eiv;
        s = (int)p[e];
        d = (int)p[(size_t)EE + e];
    } else {
        const int* p = (const int*)eiv;
        s = p[e];
        d = p[(size_t)EE + e];
    }
    g_sd[e] = make_int2(s, d);
    atomicAdd(g_deg + d, 1);
}

// ------------------------- 2-level exclusive scan of degrees -------------------
__global__ __launch_bounds__(1024) void k_scan1() {
    __shared__ int sm[1024];
    int t = threadIdx.x, b = blockIdx.x;
    int i = b * 1024 + t;
    int v = (i < NN) ? g_deg[i] : 0;
    sm[t] = v;
    __syncthreads();
    for (int off = 1; off < 1024; off <<= 1) {
        int x = (t >= off) ? sm[t - off] : 0;
        __syncthreads();
        sm[t] += x;
        __syncthreads();
    }
    if (i < NN) g_partial[i] = sm[t];
    if (t == 1023) g_bsum[b] = sm[t];
}
__global__ void k_scan2() {
    __shared__ int sm[128];
    int t = threadIdx.x;
    sm[t] = (t < NB1) ? g_bsum[t] : 0;
    __syncthreads();
    for (int off = 1; off < 128; off <<= 1) {
        int x = (t >= off) ? sm[t - off] : 0;
        __syncthreads();
        sm[t] += x;
        __syncthreads();
    }
    if (t < NB1) g_boff[t] = sm[t];
}
__global__ __launch_bounds__(1024) void k_scan3() {
    int t = threadIdx.x, b = blockIdx.x;
    int i = b * 1024 + t;
    if (i >= NN) return;
    int base = (b > 0) ? g_boff[b - 1] : 0;
    int incl = g_partial[i] + base;
    g_rowptr[i + 1] = incl;
    g_cur[i] = incl - g_deg[i];
    if (i == 0) g_rowptr[0] = 0;
}
__global__ void k_scatter() {
    int e = blockIdx.x * 256 + threadIdx.x;
    if (e >= EE) return;
    int2 sd = g_sd[e];
    int pos = atomicAdd(g_cur + sd.y, 1);
    g_csr[pos] = sd;
    g_eid[pos] = e;
}

// ------------------------- precompute folded edge weights --------------------
__global__ void k_pre(const float* __restrict__ We1, const float* __restrict__ atte1,
                      const float* __restrict__ We2, const float* __restrict__ atte2) {
    int t = threadIdx.x;
    if (t < 128) {
        int d = t >> 3, h = t & 7;
        float s = 0.f;
        #pragma unroll
        for (int c = 0; c < 16; ++c) s += We1[d * 128 + h * 16 + c] * atte1[h * 16 + c];
        g_Ae1[t] = s;
    }
    if (t < 16) {
        float s = 0.f;
        #pragma unroll
        for (int c = 0; c < 16; ++c) s += We2[t * 16 + c] * atte2[c];
        g_ae2w[t] = s;
    }
}

// ------------------------- GEMM1 (f32x2) + fused attention scores ------------
// thread (tr,tc): rows rb+tr*4..+3, cols {tc*4..tc*4+3} and {64+tc*4..+3}
__global__ __launch_bounds__(256) void k_gemm1(const float* __restrict__ X,
                                               const float* __restrict__ W,
                                               const float* __restrict__ atts,
                                               const float* __restrict__ attd) {
    __shared__ __align__(16) float xs[64 * 36];    // 64 rows x (32 k + 4 pad)
    __shared__ __align__(16) float ws[32 * 128];   // 32 k x 128 cols
    __shared__ float sat[128], sad[128];
    int rb = blockIdx.x * 64;
    int t = threadIdx.x;
    int tc = t & 15, tr = t >> 4;
    if (t < 128) { sat[t] = atts[t]; sad[t] = attd[t]; }

    ull acc2[4][4];
    #pragma unroll
    for (int i = 0; i < 4; ++i)
        #pragma unroll
        for (int j = 0; j < 4; ++j) acc2[i][j] = 0ull;

    for (int kt = 0; kt < 128; kt += 32) {
        __syncthreads();
        #pragma unroll
        for (int i = t; i < 512; i += 256) {       // X tile: 64x32
            int r = i >> 3, c4 = i & 7;
            int row = rb + r;
            float4 v = make_float4(0.f, 0.f, 0.f, 0.f);
            if (row < NN) v = *(const float4*)(X + (size_t)row * 128 + kt + c4 * 4);
            *(float4*)(xs + r * 36 + c4 * 4) = v;
        }
        #pragma unroll
        for (int i = t; i < 1024; i += 256) {      // W tile: 32x128
            int k = i >> 5, c4 = i & 31;
            *(float4*)(ws + k * 128 + c4 * 4) =
                *(const float4*)(W + (size_t)(kt + k) * 128 + c4 * 4);
        }
        __syncthreads();
        #pragma unroll 4
        for (int k = 0; k < 32; ++k) {
            float4 wa = *(const float4*)(ws + k * 128 + tc * 4);
            float4 wb = *(const float4*)(ws + k * 128 + 64 + tc * 4);
            ull w0 = pk2(wa.x, wa.y), w1 = pk2(wa.z, wa.w);
            ull w2 = pk2(wb.x, wb.y), w3 = pk2(wb.z, wb.w);
            #pragma unroll
            for (int i = 0; i < 4; ++i) {
                float a = xs[(tr * 4 + i) * 36 + k];
                ull aa = pk2(a, a);
                fma2(acc2[i][0], aa, w0);
                fma2(acc2[i][1], aa, w1);
                fma2(acc2[i][2], aa, w2);
                fma2(acc2[i][3], aa, w3);
            }
        }
    }

    // unpack, write xh1, fused per-head attention dots
    int ha = tc >> 2;          // head of col group A
    int hb = 4 + (tc >> 2);    // head of col group B
    #pragma unroll
    for (int i = 0; i < 4; ++i) {
        int row = rb + tr * 4 + i;
        float2 p0 = up2(acc2[i][0]), p1 = up2(acc2[i][1]);
        float2 p2 = up2(acc2[i][2]), p3 = up2(acc2[i][3]);
        float ra[4] = {p0.x, p0.y, p1.x, p1.y};
        float rbv[4] = {p2.x, p2.y, p3.x, p3.y};
        if (row < NN) {
            *(float4*)(g_xh1 + (size_t)row * 128 + tc * 4) =
                make_float4(ra[0], ra[1], ra[2], ra[3]);
            *(float4*)(g_xh1 + (size_t)row * 128 + 64 + tc * 4) =
                make_float4(rbv[0], rbv[1], rbv[2], rbv[3]);
        }
        float psa = 0.f, pda = 0.f, psb = 0.f, pdb = 0.f;
        #pragma unroll
        for (int j = 0; j < 4; ++j) {
            psa += ra[j] * sat[tc * 4 + j];
            pda += ra[j] * sad[tc * 4 + j];
            psb += rbv[j] * sat[64 + tc * 4 + j];
            pdb += rbv[j] * sad[64 + tc * 4 + j];
        }
        // reduce over the 4 threads sharing (tc>>2)
        #pragma unroll
        for (int off = 1; off <= 2; off <<= 1) {
            psa += __shfl_xor_sync(0xffffffffu, psa, off);
            pda += __shfl_xor_sync(0xffffffffu, pda, off);
            psb += __shfl_xor_sync(0xffffffffu, psb, off);
            pdb += __shfl_xor_sync(0xffffffffu, pdb, off);
        }
        if ((tc & 3) == 0 && row < NN) {
            g_as1[(size_t)row * 8 + ha] = psa;
            g_ad1[(size_t)row * 8 + ha] = pda;
            g_as1[(size_t)row * 8 + hb] = psb;
            g_ad1[(size_t)row * 8 + hb] = pdb;
        }
    }
}

// ------------------------- edge pass A (CSR order): logits + global max ------
__global__ __launch_bounds__(256) void k_edgeA(const float* __restrict__ ea) {
    __shared__ float sA[128];
    __shared__ float sE[16];
    __shared__ float wmax[8];
    int t = threadIdx.x;
    if (t < 128) sA[t] = g_Ae1[t];
    if (t < 16)  sE[t] = g_ae2w[t];
    __syncthreads();
    int p = blockIdx.x * 256 + t;
    float mt = -1e30f;
    if (p < EE) {
        int2 sd = g_csr[p];
        int eid = g_eid[p];
        int s = sd.x, d = sd.y;
        float ev[16];
        {
            const float4* ep = (const float4*)(ea + (size_t)eid * 16);
            ((float4*)ev)[0] = __ldg(ep);     ((float4*)ev)[1] = __ldg(ep + 1);
            ((float4*)ev)[2] = __ldg(ep + 2); ((float4*)ev)[3] = __ldg(ep + 3);
        }
        float aeh[8] = {0, 0, 0, 0, 0, 0, 0, 0};
        float a2 = 0.f;
        #pragma unroll
        for (int dd = 0; dd < 16; ++dd) {
            float v = ev[dd];
            a2 += v * sE[dd];
            #pragma unroll
            for (int h = 0; h < 8; ++h) aeh[h] += v * sA[dd * 8 + h];
        }
        float4 s0 = *(const float4*)(g_as1 + (size_t)s * 8);
        float4 s1v = *(const float4*)(g_as1 + (size_t)s * 8 + 4);
        float4 d0 = *(const float4*)(g_ad1 + (size_t)d * 8);
        float4 d1v = *(const float4*)(g_ad1 + (size_t)d * 8 + 4);
        float al[8];
        al[0] = lrelu(s0.x + d0.x + aeh[0]);   al[1] = lrelu(s0.y + d0.y + aeh[1]);
        al[2] = lrelu(s0.z + d0.z + aeh[2]);   al[3] = lrelu(s0.w + d0.w + aeh[3]);
        al[4] = lrelu(s1v.x + d1v.x + aeh[4]); al[5] = lrelu(s1v.y + d1v.y + aeh[5]);
        al[6] = lrelu(s1v.z + d1v.z + aeh[6]); al[7] = lrelu(s1v.w + d1v.w + aeh[7]);
        *(float4*)(g_alpha1 + (size_t)p * 8)     = make_float4(al[0], al[1], al[2], al[3]);
        *(float4*)(g_alpha1 + (size_t)p * 8 + 4) = make_float4(al[4], al[5], al[6], al[7]);
        g_ae2e[p] = a2;
        #pragma unroll
        for (int h = 0; h < 8; ++h) mt = fmaxf(mt, al[h]);
    }
    #pragma unroll
    for (int off = 16; off > 0; off >>= 1)
        mt = fmaxf(mt, __shfl_xor_sync(0xffffffffu, mt, off));
    if ((t & 31) == 0) wmax[t >> 5] = mt;
    __syncthreads();
    if (t < 8) {
        float v = wmax[t];
        #pragma unroll
        for (int off = 4; off > 0; off >>= 1)
            v = fmaxf(v, __shfl_xor_sync(0x000000ffu, v, off));
        if (t == 0) atomicMax(&g_gm1i, enc_f(v));
    }
}

// ------------------------- layer-1 aggregation: warp per dst, pipelined ------
__global__ __launch_bounds__(256) void k_agg1(const float* __restrict__ b1) {
    int gw = (blockIdx.x * 256 + threadIdx.x) >> 5;
    int lane = threadIdx.x & 31;
    if (gw >= NN) return;
    int start = g_rowptr[gw], end = g_rowptr[gw + 1];
    float gm = dec_f(g_gm1i);
    float sum = 0.f;
    float4 acc = make_float4(0.f, 0.f, 0.f, 0.f);
    int src_n = 0;
    float av_n = 0.f;
    if (start < end) {
        src_n = g_csr[start].x;
        av_n = (lane < 8) ? g_alpha1[(size_t)start * 8 + lane] : 0.f;
    }
    for (int j = start; j < end; ++j) {
        int src = src_n;
        float av = av_n;
        if (j + 1 < end) {
            src_n = g_csr[j + 1].x;
            av_n = (lane < 8) ? g_alpha1[(size_t)(j + 1) * 8 + lane] : 0.f;
        }
        float4 v = *(const float4*)(g_xh1 + (size_t)src * 128 + lane * 4);
        float ex = __expf(av - gm);
        if (lane < 8) sum += ex;
        float w = __shfl_sync(0xffffffffu, ex, lane >> 2);
        acc.x += w * v.x; acc.y += w * v.y; acc.z += w * v.z; acc.w += w * v.w;
    }
    float s = __shfl_sync(0xffffffffu, sum, lane >> 2) + 1e-16f;
    float4 b = *(const float4*)(b1 + lane * 4);
    float4 o;
    o.x = acc.x / s + b.x; o.y = acc.y / s + b.y;
    o.z = acc.z / s + b.z; o.w = acc.w / s + b.w;
    o.x = o.x > 0.f ? o.x : expm1f(o.x);
    o.y = o.y > 0.f ? o.y : expm1f(o.y);
    o.z = o.z > 0.f ? o.z : expm1f(o.z);
    o.w = o.w > 0.f ? o.w : expm1f(o.w);
    *(float4*)(g_h1 + (size_t)gw * 128 + lane * 4) = o;
}

// ------------------------- GEMM2: xh2 = h1 @ W2, plus a_s2/a_d2 --------------
__global__ __launch_bounds__(256) void k_gemm2(const float* __restrict__ W2,
                                               const float* __restrict__ atts,
                                               const float* __restrict__ attd) {
    __shared__ float xs[64 * 132];
    __shared__ float ws[128 * 16];
    __shared__ float sh2[64 * 16];
    __shared__ float sa[16], sdv[16];
    int rb = blockIdx.x * 64;
    int t = threadIdx.x;
    {
        int lane = t & 31, w0 = t >> 5;
        for (int r = w0; r < 64; r += 8) {
            int row = rb + r;
            float4 v = make_float4(0.f, 0.f, 0.f, 0.f);
            if (row < NN) v = ((const float4*)(g_h1 + (size_t)row * 128))[lane];
            *(float4*)(xs + r * 132 + lane * 4) = v;
        }
    }
    for (int i = t; i < 128 * 4; i += 256) {
        int k = i >> 2, c4 = i & 3;
        *(float4*)(ws + k * 16 + c4 * 4) = *(const float4*)(W2 + k * 16 + c4 * 4);
    }
    if (t < 16) { sa[t] = atts[t]; sdv[t] = attd[t]; }
    __syncthreads();
    int tc = t & 15, tr = t >> 4;
    float acc[4] = {0, 0, 0, 0};
    #pragma unroll 4
    for (int k = 0; k < 128; ++k) {
        float w = ws[k * 16 + tc];
        acc[0] += xs[(tr * 4 + 0) * 132 + k] * w;
        acc[1] += xs[(tr * 4 + 1) * 132 + k] * w;
        acc[2] += xs[(tr * 4 + 2) * 132 + k] * w;
        acc[3] += xs[(tr * 4 + 3) * 132 + k] * w;
    }
    #pragma unroll
    for (int i = 0; i < 4; ++i) {
        int r = tr * 4 + i, row = rb + r;
        sh2[r * 16 + tc] = acc[i];
        if (row < NN) g_xh2[(size_t)row * 16 + tc] = acc[i];
    }
    __syncthreads();
    if (t < 64) {
        int row = rb + t;
        if (row < NN) {
            float s = 0.f, d = 0.f;
            #pragma unroll
            for (int c = 0; c < 16; ++c) {
                float v = sh2[t * 16 + c];
                s += v * sa[c];
                d += v * sdv[c];
            }
            g_as2[row] = s;
            g_ad2[row] = d;
        }
    }
}

// ------------------------- edge pass C (CSR order): logits + global max ------
__global__ __launch_bounds__(256) void k_edgeC() {
    __shared__ float wmax[8];
    int t = threadIdx.x;
    int p = blockIdx.x * 256 + t;
    float a = -1e30f;
    if (p < EE) {
        int2 sd = g_csr[p];
        a = lrelu(g_as2[sd.x] + g_ad2[sd.y] + g_ae2e[p]);
        g_alpha2[p] = a;
    }
    #pragma unroll
    for (int off = 16; off > 0; off >>= 1)
        a = fmaxf(a, __shfl_xor_sync(0xffffffffu, a, off));
    if ((t & 31) == 0) wmax[t >> 5] = a;
    __syncthreads();
    if (t < 8) {
        float v = wmax[t];
        #pragma unroll
        for (int off = 4; off > 0; off >>= 1)
            v = fmaxf(v, __shfl_xor_sync(0x000000ffu, v, off));
        if (t == 0) atomicMax(&g_gm2i, enc_f(v));
    }
}

// ------------------------- layer-2 aggregation + log_softmax -----------------
__global__ __launch_bounds__(256) void k_agg2(const float* __restrict__ b2,
                                              float* __restrict__ out) {
    int d = blockIdx.x * 16 + (threadIdx.x >> 4);
    int l = threadIdx.x & 15;
    if (d >= NN) return;
    int start = g_rowptr[d], end = g_rowptr[d + 1];
    float gm = dec_f(g_gm2i);
    float sum = 0.f, acc = 0.f;
    for (int j = start; j < end; ++j) {
        int src = g_csr[j].x;
        float ex = __expf(g_alpha2[j] - gm);
        sum += ex;
        acc += ex * g_xh2[(size_t)src * 16 + l];
    }
    float o = acc / (sum + 1e-16f) + b2[l];
    float m = o;
    #pragma unroll
    for (int off = 8; off > 0; off >>= 1)
        m = fmaxf(m, __shfl_xor_sync(0xffffffffu, m, off, 16));
    float e2 = __expf(o - m), s2 = e2;
    #pragma unroll
    for (int off = 8; off > 0; off >>= 1)
        s2 += __shfl_xor_sync(0xffffffffu, s2, off, 16);
    out[(size_t)d * 16 + l] = o - (m + logf(s2));
}

// ------------------------- launch --------------------------------------------
extern "C" void kernel_launch(void* const* d_in, const int* in_sizes, int n_in,
                              void* d_out, int out_size) {
    const float* x     = (const float*)d_in[0];
    const void*  ei    = d_in[1];
    const float* ea    = (const float*)d_in[2];
    const float* W1    = (const float*)d_in[3];
    const float* atts1 = (const float*)d_in[4];
    const float* attd1 = (const float*)d_in[5];
    const float* We1   = (const float*)d_in[6];
    const float* atte1 = (const float*)d_in[7];
    const float* b1    = (const float*)d_in[8];
    const float* W2    = (const float*)d_in[9];
    const float* atts2 = (const float*)d_in[10];
    const float* attd2 = (const float*)d_in[11];
    const float* We2   = (const float*)d_in[12];
    const float* atte2 = (const float*)d_in[13];
    const float* b2    = (const float*)d_in[14];
    float* out = (float*)d_out;

    k_detect<<<1, 32>>>((const int*)ei);
    k_zero<<<(NN + 255) / 256, 256>>>();
    k_gather<<<(EE + 255) / 256, 256>>>(ei);
    k_scan1<<<NB1, 1024>>>();
    k_scan2<<<1, 128>>>();
    k_scan3<<<NB1, 1024>>>();
    k_scatter<<<(EE + 255) / 256, 256>>>();
    k_pre<<<1, 128>>>(We1, atte1, We2, atte2);

    k_gemm1<<<(NN + 63) / 64, 256>>>(x, W1, atts1, attd1);
    k_edgeA<<<(EE + 255) / 256, 256>>>(ea);
    k_agg1<<<(NN * 32 + 255) / 256, 256>>>(b1);
    k_gemm2<<<(NN + 63) / 64, 256>>>(W2, atts2, attd2);
    k_edgeC<<<(EE + 255) / 256, 256>>>();
    k_agg2<<<(NN * 16 + 255) / 256, 256>>>(b2, out);
}

// round 17
// speedup vs baseline: 2.4455x; 1.0569x over previous
#include <cuda_runtime.h>
#include <cuda_fp16.h>
#include <math.h>
#include <limits.h>

#define NN   100000
#define EE   1600000
#define FIN  128
#define EDIM 16
#define NH1  8
#define HID  16
#define D1   128
#define C2   16
#define NB1  98          // ceil(NN / 1024)

typedef unsigned long long ull;

// ------------------------- scratch (device globals; no allocs) ---------------
__device__ __align__(16) __half g_xh1h[(size_t)NN * 128];  // fp16 message table
__device__ __align__(16) float g_as1[(size_t)NN * 8];
__device__ __align__(16) float g_ad1[(size_t)NN * 8];
__device__ __align__(16) float g_alpha1[(size_t)EE * 8];   // CSR order
__device__ __align__(16) float g_ae2e[(size_t)EE];         // CSR order
__device__ __align__(16) float g_h1 [(size_t)NN * 128];
__device__ __align__(16) float g_xh2[(size_t)NN * 16];
__device__ __align__(16) float g_as2[(size_t)NN];
__device__ __align__(16) float g_ad2[(size_t)NN];
__device__ __align__(16) float g_alpha2[(size_t)EE];       // CSR order
__device__ __align__(16) float g_Ae1[16 * 8];
__device__ __align__(16) float g_ae2w[16];
__device__ __align__(16) int2  g_sd [(size_t)EE];          // (src, dst) edge order
__device__ __align__(16) int2  g_csr[(size_t)EE];          // (src, dst) CSR order
__device__ __align__(16) int   g_eid[(size_t)EE];          // original edge id, CSR order
__device__ __align__(16) int   g_deg[NN];
__device__ __align__(16) int   g_partial[NN];
__device__ __align__(16) int   g_bsum[NB1];
__device__ __align__(16) int   g_boff[NB1];
__device__ __align__(16) int   g_rowptr[NN + 1];
__device__ __align__(16) int   g_cur[NN];
__device__ int g_gm1i;
__device__ int g_gm2i;
__device__ int g_is64;

// ------------------------- helpers -------------------------------------------
__device__ __forceinline__ int enc_f(float f) {
    int i = __float_as_int(f);
    return i >= 0 ? i : (i ^ 0x7FFFFFFF);
}
__device__ __forceinline__ float dec_f(int i) {
    return __int_as_float(i >= 0 ? i : (i ^ 0x7FFFFFFF));
}
__device__ __forceinline__ float lrelu(float a) { return a >= 0.f ? a : 0.2f * a; }

// packed f32x2 ops (sm_103a FFMA2 path)
__device__ __forceinline__ ull pk2(float lo, float hi) {
    ull d; asm("mov.b64 %0, {%1, %2};" : "=l"(d) : "f"(lo), "f"(hi)); return d;
}
__device__ __forceinline__ void fma2(ull& d, ull a, ull b) {
    asm("fma.rn.f32x2 %0, %1, %2, %0;" : "+l"(d) : "l"(a), "l"(b));
}
__device__ __forceinline__ float2 up2(ull d) {
    float2 r; asm("mov.b64 {%0, %1}, %2;" : "=f"(r.x), "=f"(r.y) : "l"(d)); return r;
}

// ------------------------- edge_index dtype detection ------------------------
__global__ void k_detect(const int* __restrict__ eib) {
    if (threadIdx.x == 0) {
        int all0 = 1;
        #pragma unroll 8
        for (int i = 0; i < 64; ++i)
            if (eib[2 * i + 1] != 0) all0 = 0;
        g_is64 = all0;
    }
}

__global__ void k_zero() {
    int i = blockIdx.x * 256 + threadIdx.x;
    if (i < NN) g_deg[i] = 0;
    if (i == 0) { g_gm1i = INT_MIN; g_gm2i = INT_MIN; }
}

// ------------------------- canonicalize + histogram ---------------------------
__global__ void k_gather(const void* __restrict__ eiv) {
    int e = blockIdx.x * 256 + threadIdx.x;
    if (e >= EE) return;
    int s, d;
    if (g_is64) {
        const long long* p = (const long long*)eiv;
        s = (int)p[e];
        d = (int)p[(size_t)EE + e];
    } else {
        const int* p = (const int*)eiv;
        s = p[e];
        d = p[(size_t)EE + e];
    }
    g_sd[e] = make_int2(s, d);
    atomicAdd(g_deg + d, 1);
}

// ------------------------- 2-level exclusive scan of degrees -------------------
__global__ __launch_bounds__(1024) void k_scan1() {
    __shared__ int sm[1024];
    int t = threadIdx.x, b = blockIdx.x;
    int i = b * 1024 + t;
    int v = (i < NN) ? g_deg[i] : 0;
    sm[t] = v;
    __syncthreads();
    for (int off = 1; off < 1024; off <<= 1) {
        int x = (t >= off) ? sm[t - off] : 0;
        __syncthreads();
        sm[t] += x;
        __syncthreads();
    }
    if (i < NN) g_partial[i] = sm[t];
    if (t == 1023) g_bsum[b] = sm[t];
}
__global__ void k_scan2() {
    __shared__ int sm[128];
    int t = threadIdx.x;
    sm[t] = (t < NB1) ? g_bsum[t] : 0;
    __syncthreads();
    for (int off = 1; off < 128; off <<= 1) {
        int x = (t >= off) ? sm[t - off] : 0;
        __syncthreads();
        sm[t] += x;
        __syncthreads();
    }
    if (t < NB1) g_boff[t] = sm[t];
}
__global__ __launch_bounds__(1024) void k_scan3() {
    int t = threadIdx.x, b = blockIdx.x;
    int i = b * 1024 + t;
    if (i >= NN) return;
    int base = (b > 0) ? g_boff[b - 1] : 0;
    int incl = g_partial[i] + base;
    g_rowptr[i + 1] = incl;
    g_cur[i] = incl - g_deg[i];
    if (i == 0) g_rowptr[0] = 0;
}
__global__ void k_scatter() {
    int e = blockIdx.x * 256 + threadIdx.x;
    if (e >= EE) return;
    int2 sd = g_sd[e];
    int pos = atomicAdd(g_cur + sd.y, 1);
    g_csr[pos] = sd;
    g_eid[pos] = e;
}

// ------------------------- precompute folded edge weights --------------------
__global__ void k_pre(const float* __restrict__ We1, const float* __restrict__ atte1,
                      const float* __restrict__ We2, const float* __restrict__ atte2) {
    int t = threadIdx.x;
    if (t < 128) {
        int d = t >> 3, h = t & 7;
        float s = 0.f;
        #pragma unroll
        for (int c = 0; c < 16; ++c) s += We1[d * 128 + h * 16 + c] * atte1[h * 16 + c];
        g_Ae1[t] = s;
    }
    if (t < 16) {
        float s = 0.f;
        #pragma unroll
        for (int c = 0; c < 16; ++c) s += We2[t * 16 + c] * atte2[c];
        g_ae2w[t] = s;
    }
}

// ------------------------- GEMM1 (f32x2) + fused attention scores ------------
// thread (tr,tc): rows rb+tr*4..+3, cols {tc*4..tc*4+3} and {64+tc*4..+3}
// writes fp16 message table g_xh1h; att scores from fp32 registers
__global__ __launch_bounds__(256) void k_gemm1(const float* __restrict__ X,
                                               const float* __restrict__ W,
                                               const float* __restrict__ atts,
                                               const float* __restrict__ attd) {
    __shared__ __align__(16) float xs[64 * 36];    // 64 rows x (32 k + 4 pad)
    __shared__ __align__(16) float ws[32 * 128];   // 32 k x 128 cols
    __shared__ float sat[128], sad[128];
    int rb = blockIdx.x * 64;
    int t = threadIdx.x;
    int tc = t & 15, tr = t >> 4;
    if (t < 128) { sat[t] = atts[t]; sad[t] = attd[t]; }

    ull acc2[4][4];
    #pragma unroll
    for (int i = 0; i < 4; ++i)
        #pragma unroll
        for (int j = 0; j < 4; ++j) acc2[i][j] = 0ull;

    for (int kt = 0; kt < 128; kt += 32) {
        __syncthreads();
        #pragma unroll
        for (int i = t; i < 512; i += 256) {       // X tile: 64x32
            int r = i >> 3, c4 = i & 7;
            int row = rb + r;
            float4 v = make_float4(0.f, 0.f, 0.f, 0.f);
            if (row < NN) v = *(const float4*)(X + (size_t)row * 128 + kt + c4 * 4);
            *(float4*)(xs + r * 36 + c4 * 4) = v;
        }
        #pragma unroll
        for (int i = t; i < 1024; i += 256) {      // W tile: 32x128
            int k = i >> 5, c4 = i & 31;
            *(float4*)(ws + k * 128 + c4 * 4) =
                *(const float4*)(W + (size_t)(kt + k) * 128 + c4 * 4);
        }
        __syncthreads();
        #pragma unroll 4
        for (int k = 0; k < 32; ++k) {
            float4 wa = *(const float4*)(ws + k * 128 + tc * 4);
            float4 wb = *(const float4*)(ws + k * 128 + 64 + tc * 4);
            ull w0 = pk2(wa.x, wa.y), w1 = pk2(wa.z, wa.w);
            ull w2 = pk2(wb.x, wb.y), w3 = pk2(wb.z, wb.w);
            #pragma unroll
            for (int i = 0; i < 4; ++i) {
                float a = xs[(tr * 4 + i) * 36 + k];
                ull aa = pk2(a, a);
                fma2(acc2[i][0], aa, w0);
                fma2(acc2[i][1], aa, w1);
                fma2(acc2[i][2], aa, w2);
                fma2(acc2[i][3], aa, w3);
            }
        }
    }

    int ha = tc >> 2;
    int hb = 4 + (tc >> 2);
    #pragma unroll
    for (int i = 0; i < 4; ++i) {
        int row = rb + tr * 4 + i;
        float2 p0 = up2(acc2[i][0]), p1 = up2(acc2[i][1]);
        float2 p2 = up2(acc2[i][2]), p3 = up2(acc2[i][3]);
        float ra[4] = {p0.x, p0.y, p1.x, p1.y};
        float rbv[4] = {p2.x, p2.y, p3.x, p3.y};
        if (row < NN) {
            // fp16 message table: 4 halves = 8 bytes per col-group
            half2 ha0 = __floats2half2_rn(ra[0], ra[1]);
            half2 ha1 = __floats2half2_rn(ra[2], ra[3]);
            half2 hb0 = __floats2half2_rn(rbv[0], rbv[1]);
            half2 hb1 = __floats2half2_rn(rbv[2], rbv[3]);
            *(half2*)(g_xh1h + (size_t)row * 128 + tc * 4)          = ha0;
            *(half2*)(g_xh1h + (size_t)row * 128 + tc * 4 + 2)      = ha1;
            *(half2*)(g_xh1h + (size_t)row * 128 + 64 + tc * 4)     = hb0;
            *(half2*)(g_xh1h + (size_t)row * 128 + 64 + tc * 4 + 2) = hb1;
        }
        float psa = 0.f, pda = 0.f, psb = 0.f, pdb = 0.f;
        #pragma unroll
        for (int j = 0; j < 4; ++j) {
            psa += ra[j] * sat[tc * 4 + j];
            pda += ra[j] * sad[tc * 4 + j];
            psb += rbv[j] * sat[64 + tc * 4 + j];
            pdb += rbv[j] * sad[64 + tc * 4 + j];
        }
        #pragma unroll
        for (int off = 1; off <= 2; off <<= 1) {
            psa += __shfl_xor_sync(0xffffffffu, psa, off);
            pda += __shfl_xor_sync(0xffffffffu, pda, off);
            psb += __shfl_xor_sync(0xffffffffu, psb, off);
            pdb += __shfl_xor_sync(0xffffffffu, pdb, off);
        }
        if ((tc & 3) == 0 && row < NN) {
            g_as1[(size_t)row * 8 + ha] = psa;
            g_ad1[(size_t)row * 8 + ha] = pda;
            g_as1[(size_t)row * 8 + hb] = psb;
            g_ad1[(size_t)row * 8 + hb] = pdb;
        }
    }
}

// ------------------------- edge pass A (CSR order): logits + global max ------
__global__ __launch_bounds__(256) void k_edgeA(const float* __restrict__ ea) {
    __shared__ float sA[128];
    __shared__ float sE[16];
    __shared__ float wmax[8];
    int t = threadIdx.x;
    if (t < 128) sA[t] = g_Ae1[t];
    if (t < 16)  sE[t] = g_ae2w[t];
    __syncthreads();
    int p = blockIdx.x * 256 + t;
    float mt = -1e30f;
    if (p < EE) {
        int2 sd = g_csr[p];
        int eid = g_eid[p];
        int s = sd.x, d = sd.y;
        float ev[16];
        {
            const float4* ep = (const float4*)(ea + (size_t)eid * 16);
            ((float4*)ev)[0] = __ldg(ep);     ((float4*)ev)[1] = __ldg(ep + 1);
            ((float4*)ev)[2] = __ldg(ep + 2); ((float4*)ev)[3] = __ldg(ep + 3);
        }
        float aeh[8] = {0, 0, 0, 0, 0, 0, 0, 0};
        float a2 = 0.f;
        #pragma unroll
        for (int dd = 0; dd < 16; ++dd) {
            float v = ev[dd];
            a2 += v * sE[dd];
            #pragma unroll
            for (int h = 0; h < 8; ++h) aeh[h] += v * sA[dd * 8 + h];
        }
        float4 s0 = *(const float4*)(g_as1 + (size_t)s * 8);
        float4 s1v = *(const float4*)(g_as1 + (size_t)s * 8 + 4);
        float4 d0 = *(const float4*)(g_ad1 + (size_t)d * 8);
        float4 d1v = *(const float4*)(g_ad1 + (size_t)d * 8 + 4);
        float al[8];
        al[0] = lrelu(s0.x + d0.x + aeh[0]);   al[1] = lrelu(s0.y + d0.y + aeh[1]);
        al[2] = lrelu(s0.z + d0.z + aeh[2]);   al[3] = lrelu(s0.w + d0.w + aeh[3]);
        al[4] = lrelu(s1v.x + d1v.x + aeh[4]); al[5] = lrelu(s1v.y + d1v.y + aeh[5]);
        al[6] = lrelu(s1v.z + d1v.z + aeh[6]); al[7] = lrelu(s1v.w + d1v.w + aeh[7]);
        *(float4*)(g_alpha1 + (size_t)p * 8)     = make_float4(al[0], al[1], al[2], al[3]);
        *(float4*)(g_alpha1 + (size_t)p * 8 + 4) = make_float4(al[4], al[5], al[6], al[7]);
        g_ae2e[p] = a2;
        #pragma unroll
        for (int h = 0; h < 8; ++h) mt = fmaxf(mt, al[h]);
    }
    #pragma unroll
    for (int off = 16; off > 0; off >>= 1)
        mt = fmaxf(mt, __shfl_xor_sync(0xffffffffu, mt, off));
    if ((t & 31) == 0) wmax[t >> 5] = mt;
    __syncthreads();
    if (t < 8) {
        float v = wmax[t];
        #pragma unroll
        for (int off = 4; off > 0; off >>= 1)
            v = fmaxf(v, __shfl_xor_sync(0x000000ffu, v, off));
        if (t == 0) atomicMax(&g_gm1i, enc_f(v));
    }
}

// ------------------------- layer-1 aggregation: warp per dst, fp16 gather ----
__global__ __launch_bounds__(256) void k_agg1(const float* __restrict__ b1) {
    int gw = (blockIdx.x * 256 + threadIdx.x) >> 5;
    int lane = threadIdx.x & 31;
    if (gw >= NN) return;
    int start = g_rowptr[gw], end = g_rowptr[gw + 1];
    float gm = dec_f(g_gm1i);
    float sum = 0.f;
    float4 acc = make_float4(0.f, 0.f, 0.f, 0.f);
    int src_n = 0;
    float av_n = 0.f;
    if (start < end) {
        src_n = g_csr[start].x;
        av_n = (lane < 8) ? g_alpha1[(size_t)start * 8 + lane] : 0.f;
    }
    for (int j = start; j < end; ++j) {
        int src = src_n;
        float av = av_n;
        if (j + 1 < end) {
            src_n = g_csr[j + 1].x;
            av_n = (lane < 8) ? g_alpha1[(size_t)(j + 1) * 8 + lane] : 0.f;
        }
        // 4 halves per lane (8B), warp covers 256B row
        uint2 u = *(const uint2*)(g_xh1h + (size_t)src * 128 + lane * 4);
        float ex = __expf(av - gm);
        if (lane < 8) sum += ex;
        float w = __shfl_sync(0xffffffffu, ex, lane >> 2);
        float2 f0 = __half22float2(*(half2*)&u.x);
        float2 f1 = __half22float2(*(half2*)&u.y);
        acc.x += w * f0.x; acc.y += w * f0.y; acc.z += w * f1.x; acc.w += w * f1.y;
    }
    float s = __shfl_sync(0xffffffffu, sum, lane >> 2) + 1e-16f;
    float4 b = *(const float4*)(b1 + lane * 4);
    float4 o;
    o.x = acc.x / s + b.x; o.y = acc.y / s + b.y;
    o.z = acc.z / s + b.z; o.w = acc.w / s + b.w;
    o.x = o.x > 0.f ? o.x : expm1f(o.x);
    o.y = o.y > 0.f ? o.y : expm1f(o.y);
    o.z = o.z > 0.f ? o.z : expm1f(o.z);
    o.w = o.w > 0.f ? o.w : expm1f(o.w);
    *(float4*)(g_h1 + (size_t)gw * 128 + lane * 4) = o;
}

// ------------------------- GEMM2: xh2 = h1 @ W2, plus a_s2/a_d2 --------------
__global__ __launch_bounds__(256) void k_gemm2(const float* __restrict__ W2,
                                               const float* __restrict__ atts,
                                               const float* __restrict__ attd) {
    __shared__ float xs[64 * 132];
    __shared__ float ws[128 * 16];
    __shared__ float sh2[64 * 16];
    __shared__ float sa[16], sdv[16];
    int rb = blockIdx.x * 64;
    int t = threadIdx.x;
    {
        int lane = t & 31, w0 = t >> 5;
        for (int r = w0; r < 64; r += 8) {
            int row = rb + r;
            float4 v = make_float4(0.f, 0.f, 0.f, 0.f);
            if (row < NN) v = ((const float4*)(g_h1 + (size_t)row * 128))[lane];
            *(float4*)(xs + r * 132 + lane * 4) = v;
        }
    }
    for (int i = t; i < 128 * 4; i += 256) {
        int k = i >> 2, c4 = i & 3;
        *(float4*)(ws + k * 16 + c4 * 4) = *(const float4*)(W2 + k * 16 + c4 * 4);
    }
    if (t < 16) { sa[t] = atts[t]; sdv[t] = attd[t]; }
    __syncthreads();
    int tc = t & 15, tr = t >> 4;
    float acc[4] = {0, 0, 0, 0};
    #pragma unroll 4
    for (int k = 0; k < 128; ++k) {
        float w = ws[k * 16 + tc];
        acc[0] += xs[(tr * 4 + 0) * 132 + k] * w;
        acc[1] += xs[(tr * 4 + 1) * 132 + k] * w;
        acc[2] += xs[(tr * 4 + 2) * 132 + k] * w;
        acc[3] += xs[(tr * 4 + 3) * 132 + k] * w;
    }
    #pragma unroll
    for (int i = 0; i < 4; ++i) {
        int r = tr * 4 + i, row = rb + r;
        sh2[r * 16 + tc] = acc[i];
        if (row < NN) g_xh2[(size_t)row * 16 + tc] = acc[i];
    }
    __syncthreads();
    if (t < 64) {
        int row = rb + t;
        if (row < NN) {
            float s = 0.f, d = 0.f;
            #pragma unroll
            for (int c = 0; c < 16; ++c) {
                float v = sh2[t * 16 + c];
                s += v * sa[c];
                d += v * sdv[c];
            }
            g_as2[row] = s;
            g_ad2[row] = d;
        }
    }
}

// ------------------------- edge pass C (CSR order): logits + global max ------
__global__ __launch_bounds__(256) void k_edgeC() {
    __shared__ float wmax[8];
    int t = threadIdx.x;
    int p = blockIdx.x * 256 + t;
    float a = -1e30f;
    if (p < EE) {
        int2 sd = g_csr[p];
        a = lrelu(g_as2[sd.x] + g_ad2[sd.y] + g_ae2e[p]);
        g_alpha2[p] = a;
    }
    #pragma unroll
    for (int off = 16; off > 0; off >>= 1)
        a = fmaxf(a, __shfl_xor_sync(0xffffffffu, a, off));
    if ((t & 31) == 0) wmax[t >> 5] = a;
    __syncthreads();
    if (t < 8) {
        float v = wmax[t];
        #pragma unroll
        for (int off = 4; off > 0; off >>= 1)
            v = fmaxf(v, __shfl_xor_sync(0x000000ffu, v, off));
        if (t == 0) atomicMax(&g_gm2i, enc_f(v));
    }
}

// ------------------------- layer-2 aggregation + log_softmax -----------------
__global__ __launch_bounds__(256) void k_agg2(const float* __restrict__ b2,
                                              float* __restrict__ out) {
    int d = blockIdx.x * 16 + (threadIdx.x >> 4);
    int l = threadIdx.x & 15;
    if (d >= NN) return;
    int start = g_rowptr[d], end = g_rowptr[d + 1];
    float gm = dec_f(g_gm2i);
    float sum = 0.f, acc = 0.f;
    for (int j = start; j < end; ++j) {
        int src = g_csr[j].x;
        float ex = __expf(g_alpha2[j] - gm);
        sum += ex;
        acc += ex * g_xh2[(size_t)src * 16 + l];
    }
    float o = acc / (sum + 1e-16f) + b2[l];
    float m = o;
    #pragma unroll
    for (int off = 8; off > 0; off >>= 1)
        m = fmaxf(m, __shfl_xor_sync(0xffffffffu, m, off, 16));
    float e2 = __expf(o - m), s2 = e2;
    #pragma unroll
    for (int off = 8; off > 0; off >>= 1)
        s2 += __shfl_xor_sync(0xffffffffu, s2, off, 16);
    out[(size_t)d * 16 + l] = o - (m + logf(s2));
}

// ------------------------- launch --------------------------------------------
extern "C" void kernel_launch(void* const* d_in, const int* in_sizes, int n_in,
                              void* d_out, int out_size) {
    const float* x     = (const float*)d_in[0];
    const void*  ei    = d_in[1];
    const float* ea    = (const float*)d_in[2];
    const float* W1    = (const float*)d_in[3];
    const float* atts1 = (const float*)d_in[4];
    const float* attd1 = (const float*)d_in[5];
    const float* We1   = (const float*)d_in[6];
    const float* atte1 = (const float*)d_in[7];
    const float* b1    = (const float*)d_in[8];
    const float* W2    = (const float*)d_in[9];
    const float* atts2 = (const float*)d_in[10];
    const float* attd2 = (const float*)d_in[11];
    const float* We2   = (const float*)d_in[12];
    const float* atte2 = (const float*)d_in[13];
    const float* b2    = (const float*)d_in[14];
    float* out = (float*)d_out;

    // Order chosen so launch #6 (ncu -s 5 -c 1) is k_gemm1 — the kernel we
    // want evidence on. Dependencies preserved: scan1<-gather, scan2<-scan1,
    // scan3<-scan2, scatter<-scan3, edgeA<-{scatter, pre, gemm1}.
    k_detect<<<1, 32>>>((const int*)ei);                 // 1
    k_zero<<<(NN + 255) / 256, 256>>>();                 // 2
    k_gather<<<(EE + 255) / 256, 256>>>(ei);             // 3
    k_scan1<<<NB1, 1024>>>();                            // 4
    k_pre<<<1, 128>>>(We1, atte1, We2, atte2);           // 5
    k_gemm1<<<(NN + 63) / 64, 256>>>(x, W1, atts1, attd1); // 6  <- ncu window
    k_scan2<<<1, 128>>>();                               // 7
    k_scan3<<<NB1, 1024>>>();                            // 8
    k_scatter<<<(EE + 255) / 256, 256>>>();              // 9
    k_edgeA<<<(EE + 255) / 256, 256>>>(ea);              // 10
    k_agg1<<<(NN * 32 + 255) / 256, 256>>>(b1);          // 11
    k_gemm2<<<(NN + 63) / 64, 256>>>(W2, atts2, attd2);  // 12
    k_edgeC<<<(EE + 255) / 256, 256>>>();                // 13
    k_agg2<<<(NN * 16 + 255) / 256, 256>>>(b2, out);     // 14
}